// round 15
// baseline (speedup 1.0000x reference)
#include <cuda_runtime.h>
#include <cstdint>

#define BSZ 4
#define SEQ 2048
#define DM  512
#define NH  8
#define DKH 64
#define MR  (BSZ * SEQ)   // 8192 flattened rows
#define MWORDS (SEQ / 32) // 64 mask words per row

// Scratch (allocation-free rule: __device__ globals)
__device__ float    g_Qp[(size_t)MR * DM];
__device__ float    g_Kp[(size_t)MR * DM];
__device__ float    g_Vp[(size_t)MR * DM];
__device__ float    g_Y [(size_t)MR * DM];
__device__ float    g_W [(size_t)4 * DM * DM];   // tf32-rounded WQ|WK|WV|WO
__device__ uint32_t g_mask[(size_t)BSZ * SEQ * MWORDS];

__device__ __forceinline__ float neg_inf_f() { return __int_as_float(0xff800000u); }

__device__ __forceinline__ uint32_t f2tf(float f) {
    uint32_t u;
    asm("cvt.rna.tf32.f32 %0, %1;" : "=r"(u) : "f"(f));
    return u;
}

__device__ __forceinline__ void mma_tf32(float* c, const uint32_t* a, const uint32_t* b) {
    asm volatile(
        "mma.sync.aligned.m16n8k8.row.col.f32.tf32.tf32.f32 "
        "{%0,%1,%2,%3}, {%4,%5,%6,%7}, {%8,%9}, {%0,%1,%2,%3};\n"
        : "+f"(c[0]), "+f"(c[1]), "+f"(c[2]), "+f"(c[3])
        : "r"(a[0]), "r"(a[1]), "r"(a[2]), "r"(a[3]), "r"(b[0]), "r"(b[1]));
}

__device__ __forceinline__ void ldsm4(uint32_t* r, uint32_t addr) {
    asm volatile("ldmatrix.sync.aligned.m8n8.x4.shared.b16 {%0,%1,%2,%3}, [%4];"
        : "=r"(r[0]), "=r"(r[1]), "=r"(r[2]), "=r"(r[3]) : "r"(addr));
}

__device__ __forceinline__ uint32_t smem_u32(const void* p) {
    return (uint32_t)__cvta_generic_to_shared(p);
}

__device__ __forceinline__ void cp16(uint32_t dst, const void* src) {
    asm volatile("cp.async.cg.shared.global [%0], [%1], 16;\n"
        :: "r"(dst), "l"(src) : "memory");
}
__device__ __forceinline__ void cp_commit() {
    asm volatile("cp.async.commit_group;\n" ::: "memory");
}
__device__ __forceinline__ void cp_wait0() {
    asm volatile("cp.async.wait_group 0;\n" ::: "memory");
}
__device__ __forceinline__ void cp_wait1() {
    asm volatile("cp.async.wait_group 1;\n" ::: "memory");
}

// ---------------------------------------------------------------------------
// Prologue: tf32-round the four weight matrices into g_W.
// ---------------------------------------------------------------------------
__global__ __launch_bounds__(256) void round_w(
    const float* __restrict__ WQ, const float* __restrict__ WK,
    const float* __restrict__ WV, const float* __restrict__ WO)
{
    const int idx = blockIdx.x * 256 + threadIdx.x;       // float4 index
    const float* src = (blockIdx.y == 0) ? WQ : (blockIdx.y == 1) ? WK
                     : (blockIdx.y == 2) ? WV : WO;
    float4 v = ((const float4*)src)[idx];
    uint4 u;
    u.x = f2tf(v.x); u.y = f2tf(v.y); u.z = f2tf(v.z); u.w = f2tf(v.w);
    ((uint4*)(g_W + (size_t)blockIdx.y * DM * DM))[idx] = u;
}

// ---------------------------------------------------------------------------
// SIMT tf32 GEMM body (R7, proven): pre-rounded W (no B cvt),
// ldmatrix fragments, cp.async double-buffered k-tiles.
// Block 128x128x32, 8 warps (2x4), warp tile 64x32.
// ---------------------------------------------------------------------------
template<bool CONV_A>
__device__ __forceinline__ void gemm_body(
    const float* __restrict__ X, const float* __restrict__ W,
    const float* __restrict__ rmask, float* __restrict__ Y, int round_out,
    int row0, int col0)
{
    extern __shared__ float gsm[];
    float* Xs = gsm;                 // [2][128*36]
    float* Ws = gsm + 2 * 128 * 36;  // [2][128*36]

    const int tid  = threadIdx.x;
    const int lane = tid & 31;
    const int wid  = tid >> 5;
    const int g    = lane >> 2;
    const int tg   = lane & 3;
    const int wm   = wid >> 2;
    const int wn   = wid & 3;

    const int lr = tid >> 3;
    const int lc = (tid & 7) << 2;

    const uint32_t aoff = (((wm << 6) + (lane & 15)) * 36 + ((lane >> 4) << 2)) << 2;
    const uint32_t boff = (((wn << 5) + (lane & 7) + ((lane & 16) >> 1)) * 36
                           + ((lane & 8) >> 1)) << 2;
    const uint32_t xsBase = smem_u32(Xs);
    const uint32_t wsBase = smem_u32(Ws);

    float c[4][4][4];
#pragma unroll
    for (int mi = 0; mi < 4; mi++)
#pragma unroll
        for (int nj = 0; nj < 4; nj++)
#pragma unroll
            for (int q = 0; q < 4; q++) c[mi][nj][q] = 0.0f;

#pragma unroll
    for (int t = 0; t < 4; t++) {
        const int r = lr + (t << 5);
        cp16(smem_u32(&Xs[r * 36 + lc]), X + (size_t)(row0 + r) * DM + lc);
        cp16(smem_u32(&Ws[r * 36 + lc]), W + (size_t)(col0 + r) * DM + lc);
    }
    cp_commit();

    for (int kt = 0; kt < 16; kt++) {
        const int cur = kt & 1;
        cp_wait0();
        __syncthreads();
        if (kt + 1 < 16) {
            const int nb = cur ^ 1;
            const int k0 = (kt + 1) << 5;
#pragma unroll
            for (int t = 0; t < 4; t++) {
                const int r = lr + (t << 5);
                cp16(smem_u32(&Xs[nb * 128 * 36 + r * 36 + lc]),
                     X + (size_t)(row0 + r) * DM + k0 + lc);
                cp16(smem_u32(&Ws[nb * 128 * 36 + r * 36 + lc]),
                     W + (size_t)(col0 + r) * DM + k0 + lc);
            }
            cp_commit();
        }

        const uint32_t xb = xsBase + ((cur * 128 * 36) << 2) + aoff;
        const uint32_t wb = wsBase + ((cur * 128 * 36) << 2) + boff;
#pragma unroll
        for (int kk = 0; kk < 4; kk++) {
            const int kbb = (kk << 3) << 2;
            uint32_t a[4][4], b[2][4];
#pragma unroll
            for (int mi = 0; mi < 4; mi++) {
                ldsm4(a[mi], xb + mi * (16 * 36 * 4) + kbb);
                if (CONV_A) {
#pragma unroll
                    for (int q = 0; q < 4; q++)
                        a[mi][q] = f2tf(__uint_as_float(a[mi][q]));
                }
            }
#pragma unroll
            for (int njp = 0; njp < 2; njp++)
                ldsm4(b[njp], wb + njp * (16 * 36 * 4) + kbb);
#pragma unroll
            for (int mi = 0; mi < 4; mi++) {
                mma_tf32(c[mi][0], a[mi], b[0]);
                mma_tf32(c[mi][1], a[mi], b[0] + 2);
                mma_tf32(c[mi][2], a[mi], b[1]);
                mma_tf32(c[mi][3], a[mi], b[1] + 2);
            }
        }
        __syncthreads();
    }

#pragma unroll
    for (int mi = 0; mi < 4; mi++) {
        const int r1 = row0 + (wm << 6) + (mi << 4) + g;
        const int r2 = r1 + 8;
        const float m1 = rmask[r1];
        const float m2 = rmask[r2];
#pragma unroll
        for (int nj = 0; nj < 4; nj++) {
            const int cc = col0 + (wn << 5) + (nj << 3) + (tg << 1);
            float v[4];
            v[0] = m1 * c[mi][nj][0]; v[1] = m1 * c[mi][nj][1];
            v[2] = m2 * c[mi][nj][2]; v[3] = m2 * c[mi][nj][3];
            if (round_out) {
#pragma unroll
                for (int q = 0; q < 4; q++) v[q] = __uint_as_float(f2tf(v[q]));
            }
            float2 v1; v1.x = v[0]; v1.y = v[1];
            float2 v2; v2.x = v[2]; v2.y = v[3];
            *(float2*)(Y + (size_t)r1 * DM + cc) = v1;
            *(float2*)(Y + (size_t)r2 * DM + cc) = v2;
        }
    }
}

// ---------------------------------------------------------------------------
// Fused Q/K/V projections + mask packing.
// z in {0,1,2}: GEMM slice.  z == 3: pack att_mas bits (DRAM-bound; overlaps
// with the compute-bound GEMM waves instead of serializing as its own launch).
// ---------------------------------------------------------------------------
__global__ __launch_bounds__(256, 2) void gemm_qkv(
    const float* __restrict__ Qin, const float* __restrict__ Kin,
    const float* __restrict__ Vin,
    const float* __restrict__ qm, const float* __restrict__ km,
    const float* __restrict__ am)
{
    if (blockIdx.z == 3) {
        // mask pack: 256 CTAs x 8 warps; each warp packs 64 chunks of 128 els
        const int lane = threadIdx.x & 31;
        const size_t wbase = (size_t)(blockIdx.y * gridDim.x + blockIdx.x) * 8
                           + (threadIdx.x >> 5);          // 0..2047
        for (int i = 0; i < 64; i++) {
            const size_t wg = wbase + (size_t)i * 2048;
            const size_t base = wg * 128;
            const float v0 = am[base + lane];
            const float v1 = am[base + 32 + lane];
            const float v2 = am[base + 64 + lane];
            const float v3 = am[base + 96 + lane];
            const unsigned b0 = __ballot_sync(0xffffffffu, v0 != 0.0f);
            const unsigned b1 = __ballot_sync(0xffffffffu, v1 != 0.0f);
            const unsigned b2 = __ballot_sync(0xffffffffu, v2 != 0.0f);
            const unsigned b3 = __ballot_sync(0xffffffffu, v3 != 0.0f);
            if (lane < 4) {
                unsigned w = (lane == 0) ? b0 : (lane == 1) ? b1
                           : (lane == 2) ? b2 : b3;
                g_mask[wg * 4 + lane] = w;
            }
        }
        return;
    }
    const float* X; const float* W; const float* msk; float* Y;
    if (blockIdx.z == 0)      { X = Qin; W = g_W;               msk = qm; Y = g_Qp; }
    else if (blockIdx.z == 1) { X = Kin; W = g_W + DM * DM;     msk = km; Y = g_Kp; }
    else                      { X = Vin; W = g_W + 2 * DM * DM; msk = km; Y = g_Vp; }
    gemm_body<true>(X, W, msk, Y, 1, blockIdx.y << 7, blockIdx.x << 7);
}

// WO projection: X = g_Y (already tf32-rounded by attention), W pre-rounded.
__global__ __launch_bounds__(256, 2) void gemm_out(
    const float* __restrict__ rmask, float* __restrict__ Y)
{
    gemm_body<false>(g_Y, g_W + 3 * DM * DM, rmask, Y, 0,
                     blockIdx.y << 7, blockIdx.x << 7);
}

// ---------------------------------------------------------------------------
// TF32 flash attention, no-max softmax, SOFTWARE-PIPELINED:
//   per iter kt:  stage KV(kt+1) | exp/P(kt) | S(kt+1) | PV(kt)
// so S(kt+1)'s independent MMAs cover the P-store -> LDSM-P latency.
// 128 threads = 4 warps x 32 query rows, 2 CTAs/SM.
// Smem: PQs[128][76] (Q then P) + Ks[2][64][68] + Vs[2][64][68] = 108544 B.
// Numerics identical to R14 (same per-row op order).
// ---------------------------------------------------------------------------
__global__ __launch_bounds__(128, 2) void attn_tf32(const float* __restrict__ k_mas)
{
    extern __shared__ float smf[];
    float* PQs = smf;                                  // [128][76]  Q then P
    float* Ks  = smf + 128 * 76;                       // [2][64][68]
    float* Vs  = smf + 128 * 76 + 2 * 64 * 68;         // [2][64][68]

    const int tid  = threadIdx.x;
    const int lane = tid & 31;
    const int wid  = tid >> 5;        // 0..3
    const int g    = lane >> 2;
    const int tg   = lane & 3;
    const int q0   = blockIdx.x << 7;
    const int h    = blockIdx.y;
    const int b    = blockIdx.z;
    const int qrow = wid << 5;        // 32 query rows per warp

    const float NEGINF = neg_inf_f();

    uint32_t pqA[2];
#pragma unroll
    for (int mi = 0; mi < 2; mi++)
        pqA[mi] = smem_u32(PQs) +
            (((qrow + (mi << 4) + (lane & 15)) * 76 + ((lane >> 4) << 2)) << 2);
    const uint32_t ksB0 = smem_u32(Ks) +
        (((((lane & 7) + ((lane & 16) >> 1)) * 68) + ((lane & 8) >> 1)) << 2);

    const int lr = tid >> 4;          // 0..7
    const int lc = (tid & 15) << 2;   // 0..60

    // prologue: Q tile (group 0), K/V tile 0 (group 1)
    {
        const float* Qb = g_Qp + ((size_t)b * SEQ + q0) * DM + h * DKH;
#pragma unroll
        for (int t = 0; t < 16; t++) {
            const int r = lr + (t << 3);
            cp16(smem_u32(&PQs[r * 76 + lc]), Qb + (size_t)r * DM + lc);
        }
        cp_commit();
        const float* Kb = g_Kp + ((size_t)b * SEQ) * DM + h * DKH;
        const float* Vb = g_Vp + ((size_t)b * SEQ) * DM + h * DKH;
#pragma unroll
        for (int t = 0; t < 8; t++) {
            const int r = lr + (t << 3);
            cp16(smem_u32(&Ks[r * 68 + lc]), Kb + (size_t)r * DM + lc);
            cp16(smem_u32(&Vs[r * 68 + lc]), Vb + (size_t)r * DM + lc);
        }
        cp_commit();
    }

    cp_wait1();
    __syncthreads();
    uint32_t qf[2][8][4];
#pragma unroll
    for (int mi = 0; mi < 2; mi++)
#pragma unroll
        for (int kk = 0; kk < 8; kk++)
            ldsm4(qf[mi][kk], pqA[mi] + ((kk << 3) << 2));

    float o[2][8][4];
#pragma unroll
    for (int mi = 0; mi < 2; mi++)
#pragma unroll
        for (int dj = 0; dj < 8; dj++)
#pragma unroll
            for (int q = 0; q < 4; q++) o[mi][dj][q] = 0.0f;
    float lrow[2][2];
#pragma unroll
    for (int mi = 0; mi < 2; mi++) { lrow[mi][0] = 0.0f; lrow[mi][1] = 0.0f; }

    int qr[2][2];
#pragma unroll
    for (int mi = 0; mi < 2; mi++) {
        qr[mi][0] = q0 + qrow + (mi << 4) + g;
        qr[mi][1] = qr[mi][0] + 8;
    }

    // S(0): wait KV(0), compute into s
    float s[2][8][4];
    cp_wait0();
    __syncthreads();
    {
#pragma unroll
        for (int mi = 0; mi < 2; mi++)
#pragma unroll
            for (int nj = 0; nj < 8; nj++)
#pragma unroll
                for (int q = 0; q < 4; q++) s[mi][nj][q] = 0.0f;
#pragma unroll
        for (int kk = 0; kk < 8; kk++) {
            const int kb = kk << 3;
#pragma unroll
            for (int njp = 0; njp < 4; njp++) {
                uint32_t bb[4];
                ldsm4(bb, ksB0 + ((njp * 16 * 68 + kb) << 2));
                mma_tf32(s[0][2 * njp],     qf[0][kk], bb);
                mma_tf32(s[0][2 * njp + 1], qf[0][kk], bb + 2);
                mma_tf32(s[1][2 * njp],     qf[1][kk], bb);
                mma_tf32(s[1][2 * njp + 1], qf[1][kk], bb + 2);
            }
        }
    }

    for (int kt = 0; kt < SEQ / 64; kt++) {
        const int cur = kt & 1;
        const int nb  = cur ^ 1;

        // all warps finished PV(kt-1) (last reader of buffer nb) before restage
        __syncthreads();
        if (kt + 1 < SEQ / 64) {
            const int kk1 = (kt + 1) << 6;
            const float* Kb = g_Kp + ((size_t)b * SEQ + kk1) * DM + h * DKH;
            const float* Vb = g_Vp + ((size_t)b * SEQ + kk1) * DM + h * DKH;
#pragma unroll
            for (int t = 0; t < 8; t++) {
                const int r = lr + (t << 3);
                cp16(smem_u32(&Ks[(nb * 64 + r) * 68 + lc]), Kb + (size_t)r * DM + lc);
                cp16(smem_u32(&Vs[(nb * 64 + r) * 68 + lc]), Vb + (size_t)r * DM + lc);
            }
            cp_commit();
        }

        // mask -> exp -> partial sums -> stage P (frees the s registers)
        {
            uint2 mw[2][2];
#pragma unroll
            for (int mi = 0; mi < 2; mi++) {
                mw[mi][0] = *(const uint2*)(g_mask + ((size_t)b * SEQ + qr[mi][0]) * MWORDS + (kt << 1));
                mw[mi][1] = *(const uint2*)(g_mask + ((size_t)b * SEQ + qr[mi][1]) * MWORDS + (kt << 1));
            }
#pragma unroll
            for (int mi = 0; mi < 2; mi++) {
#pragma unroll
                for (int nj = 0; nj < 8; nj++) {
                    const int j0 = (nj << 3) + (tg << 1);
                    const uint32_t w1 = (j0 & 32) ? mw[mi][0].y : mw[mi][0].x;
                    const uint32_t w2 = (j0 & 32) ? mw[mi][1].y : mw[mi][1].x;
                    const int bi = j0 & 31;
                    const float p0 = __expf(((w1 >> bi) & 1u)       ? s[mi][nj][0] * 0.125f : NEGINF);
                    const float p1 = __expf(((w1 >> (bi + 1)) & 1u) ? s[mi][nj][1] * 0.125f : NEGINF);
                    const float p2 = __expf(((w2 >> bi) & 1u)       ? s[mi][nj][2] * 0.125f : NEGINF);
                    const float p3 = __expf(((w2 >> (bi + 1)) & 1u) ? s[mi][nj][3] * 0.125f : NEGINF);
                    lrow[mi][0] += p0 + p1;
                    lrow[mi][1] += p2 + p3;
                    const int pc = (nj << 3) + (tg << 1);
                    uint2 u1; u1.x = f2tf(p0); u1.y = f2tf(p1);
                    uint2 u2; u2.x = f2tf(p2); u2.y = f2tf(p3);
                    *(uint2*)&PQs[(qrow + (mi << 4) + g    ) * 76 + pc] = u1;
                    *(uint2*)&PQs[(qrow + (mi << 4) + 8 + g) * 76 + pc] = u2;
                }
            }
            __syncwarp();   // P visible within warp before LDSM A reads
        }

        // S(kt+1) into s (independent of P; overlaps the P round-trip)
        if (kt + 1 < SEQ / 64) {
            cp_wait0();
            __syncthreads();   // KV(kt+1) visible to all warps
#pragma unroll
            for (int mi = 0; mi < 2; mi++)
#pragma unroll
                for (int nj = 0; nj < 8; nj++)
#pragma unroll
                    for (int q = 0; q < 4; q++) s[mi][nj][q] = 0.0f;
            const uint32_t ksB = ksB0 + ((nb * 64 * 68) << 2);
#pragma unroll
            for (int kk = 0; kk < 8; kk++) {
                const int kb = kk << 3;
#pragma unroll
                for (int njp = 0; njp < 4; njp++) {
                    uint32_t bb[4];
                    ldsm4(bb, ksB + ((njp * 16 * 68 + kb) << 2));
                    mma_tf32(s[0][2 * njp],     qf[0][kk], bb);
                    mma_tf32(s[0][2 * njp + 1], qf[0][kk], bb + 2);
                    mma_tf32(s[1][2 * njp],     qf[1][kk], bb);
                    mma_tf32(s[1][2 * njp + 1], qf[1][kk], bb + 2);
                }
            }
        }

        // O += P(kt) @ V(kt)
        const float* Vb = Vs + cur * 64 * 68;
#pragma unroll
        for (int kk = 0; kk < 8; kk++) {
            const int kb = kk << 3;
            uint32_t a[2][4];
            ldsm4(a[0], pqA[0] + (kb << 2));
            ldsm4(a[1], pqA[1] + (kb << 2));
#pragma unroll
            for (int dj = 0; dj < 8; dj++) {
                uint32_t bb[2];
                bb[0] = __float_as_uint(Vb[(kb + tg    ) * 68 + (dj << 3) + g]);
                bb[1] = __float_as_uint(Vb[(kb + tg + 4) * 68 + (dj << 3) + g]);
                mma_tf32(o[0][dj], a[0], bb);
                mma_tf32(o[1][dj], a[1], bb);
            }
        }
    }

    // Epilogue: quad-reduce deferred row sums, normalize, post-mask,
    // tf32-round for the WO GEMM.
#pragma unroll
    for (int mi = 0; mi < 2; mi++) {
        float l0 = lrow[mi][0], l1 = lrow[mi][1];
        l0 += __shfl_xor_sync(0xffffffffu, l0, 1);
        l0 += __shfl_xor_sync(0xffffffffu, l0, 2);
        l1 += __shfl_xor_sync(0xffffffffu, l1, 1);
        l1 += __shfl_xor_sync(0xffffffffu, l1, 2);
        const float sc0 = k_mas[(size_t)b * SEQ + qr[mi][0]] / l0;
        const float sc1 = k_mas[(size_t)b * SEQ + qr[mi][1]] / l1;
        float* Y1 = g_Y + ((size_t)b * SEQ + qr[mi][0]) * DM + h * DKH;
        float* Y2 = g_Y + ((size_t)b * SEQ + qr[mi][1]) * DM + h * DKH;
#pragma unroll
        for (int dj = 0; dj < 8; dj++) {
            const int cc = (dj << 3) + (tg << 1);
            float2 v1, v2;
            v1.x = __uint_as_float(f2tf(o[mi][dj][0] * sc0));
            v1.y = __uint_as_float(f2tf(o[mi][dj][1] * sc0));
            v2.x = __uint_as_float(f2tf(o[mi][dj][2] * sc1));
            v2.y = __uint_as_float(f2tf(o[mi][dj][3] * sc1));
            *(float2*)(Y1 + cc) = v1;
            *(float2*)(Y2 + cc) = v2;
        }
    }
}

// ---------------------------------------------------------------------------
extern "C" void kernel_launch(void* const* d_in, const int* in_sizes, int n_in,
                              void* d_out, int out_size)
{
    (void)in_sizes; (void)n_in; (void)out_size;
    const float* Q   = (const float*)d_in[0];
    const float* K   = (const float*)d_in[1];
    const float* V   = (const float*)d_in[2];
    const float* qm  = (const float*)d_in[3];
    const float* km  = (const float*)d_in[4];
    const float* am  = (const float*)d_in[5];
    const float* WQ  = (const float*)d_in[6];
    const float* WK  = (const float*)d_in[7];
    const float* WV  = (const float*)d_in[8];
    const float* WO  = (const float*)d_in[9];
    float* out = (float*)d_out;

    const int gemm_smem = 2 * 2 * 128 * 36 * (int)sizeof(float);   // 73728
    cudaFuncSetAttribute(gemm_qkv,
                         cudaFuncAttributeMaxDynamicSharedMemorySize, gemm_smem);
    cudaFuncSetAttribute(gemm_out,
                         cudaFuncAttributeMaxDynamicSharedMemorySize, gemm_smem);

    round_w<<<dim3(DM * DM / 4 / 256, 4), 256>>>(WQ, WK, WV, WO);

    // z = 0..2: Q/K/V projection GEMMs; z = 3: mask packing (overlapped)
    gemm_qkv<<<dim3(DM / 128, MR / 128, 4), 256, gemm_smem>>>(
        Q, K, V, qm, km, am);

    const int attn_smem = (128 * 76 + 2 * 64 * 68 + 2 * 64 * 68)
                          * (int)sizeof(float);  // 108544
    cudaFuncSetAttribute(attn_tf32, cudaFuncAttributeMaxDynamicSharedMemorySize,
                         attn_smem);
    attn_tf32<<<dim3(SEQ / 128, NH, BSZ), 128, attn_smem>>>(km);

    gemm_out<<<dim3(DM / 128, MR / 128), 256, gemm_smem>>>(km, out);
}

// round 16
// speedup vs baseline: 1.7534x; 1.7534x over previous
#include <cuda_runtime.h>
#include <cstdint>

#define BSZ 4
#define SEQ 2048
#define DM  512
#define NH  8
#define DKH 64
#define MR  (BSZ * SEQ)   // 8192 flattened rows
#define MWORDS (SEQ / 32) // 64 mask words per row

// Scratch (allocation-free rule: __device__ globals)
__device__ float    g_Qp[(size_t)MR * DM];
__device__ float    g_Kp[(size_t)MR * DM];
__device__ float    g_Vp[(size_t)MR * DM];
__device__ float    g_Y [(size_t)MR * DM];
__device__ float    g_W [(size_t)4 * DM * DM];   // tf32-rounded WQ|WK|WV|WO
__device__ uint32_t g_mask[(size_t)BSZ * SEQ * MWORDS];

__device__ __forceinline__ float neg_inf_f() { return __int_as_float(0xff800000u); }

__device__ __forceinline__ uint32_t f2tf(float f) {
    uint32_t u;
    asm("cvt.rna.tf32.f32 %0, %1;" : "=r"(u) : "f"(f));
    return u;
}

__device__ __forceinline__ void mma_tf32(float* c, const uint32_t* a, const uint32_t* b) {
    asm volatile(
        "mma.sync.aligned.m16n8k8.row.col.f32.tf32.tf32.f32 "
        "{%0,%1,%2,%3}, {%4,%5,%6,%7}, {%8,%9}, {%0,%1,%2,%3};\n"
        : "+f"(c[0]), "+f"(c[1]), "+f"(c[2]), "+f"(c[3])
        : "r"(a[0]), "r"(a[1]), "r"(a[2]), "r"(a[3]), "r"(b[0]), "r"(b[1]));
}

__device__ __forceinline__ void ldsm4(uint32_t* r, uint32_t addr) {
    asm volatile("ldmatrix.sync.aligned.m8n8.x4.shared.b16 {%0,%1,%2,%3}, [%4];"
        : "=r"(r[0]), "=r"(r[1]), "=r"(r[2]), "=r"(r[3]) : "r"(addr));
}

__device__ __forceinline__ uint32_t smem_u32(const void* p) {
    return (uint32_t)__cvta_generic_to_shared(p);
}

__device__ __forceinline__ void cp16(uint32_t dst, const void* src) {
    asm volatile("cp.async.cg.shared.global [%0], [%1], 16;\n"
        :: "r"(dst), "l"(src) : "memory");
}
__device__ __forceinline__ void cp_commit() {
    asm volatile("cp.async.commit_group;\n" ::: "memory");
}
__device__ __forceinline__ void cp_wait0() {
    asm volatile("cp.async.wait_group 0;\n" ::: "memory");
}
__device__ __forceinline__ void cp_wait1() {
    asm volatile("cp.async.wait_group 1;\n" ::: "memory");
}

// ---------------------------------------------------------------------------
// Prologue: tf32-round the four weight matrices into g_W.
// ---------------------------------------------------------------------------
__global__ __launch_bounds__(256) void round_w(
    const float* __restrict__ WQ, const float* __restrict__ WK,
    const float* __restrict__ WV, const float* __restrict__ WO)
{
    const int idx = blockIdx.x * 256 + threadIdx.x;       // float4 index
    const float* src = (blockIdx.y == 0) ? WQ : (blockIdx.y == 1) ? WK
                     : (blockIdx.y == 2) ? WV : WO;
    float4 v = ((const float4*)src)[idx];
    uint4 u;
    u.x = f2tf(v.x); u.y = f2tf(v.y); u.z = f2tf(v.z); u.w = f2tf(v.w);
    ((uint4*)(g_W + (size_t)blockIdx.y * DM * DM))[idx] = u;
}

// ---------------------------------------------------------------------------
// Pack att_mas (0.0/1.0 floats) into bits (standalone, R14 config).
// ---------------------------------------------------------------------------
__global__ __launch_bounds__(256) void pack_mask(const float* __restrict__ am)
{
    const int lane = threadIdx.x & 31;
    const size_t wg = (size_t)blockIdx.x * 8 + (threadIdx.x >> 5);
    const size_t base = wg * 128;
    const float v0 = am[base + lane];
    const float v1 = am[base + 32 + lane];
    const float v2 = am[base + 64 + lane];
    const float v3 = am[base + 96 + lane];
    const unsigned b0 = __ballot_sync(0xffffffffu, v0 != 0.0f);
    const unsigned b1 = __ballot_sync(0xffffffffu, v1 != 0.0f);
    const unsigned b2 = __ballot_sync(0xffffffffu, v2 != 0.0f);
    const unsigned b3 = __ballot_sync(0xffffffffu, v3 != 0.0f);
    if (lane < 4) {
        unsigned w = (lane == 0) ? b0 : (lane == 1) ? b1 : (lane == 2) ? b2 : b3;
        g_mask[wg * 4 + lane] = w;
    }
}

// ---------------------------------------------------------------------------
// SIMT tf32 GEMM body (R7, proven): pre-rounded W (no B cvt),
// ldmatrix fragments, cp.async double-buffered k-tiles.
// Block 128x128x32, 8 warps (2x4), warp tile 64x32.
// ---------------------------------------------------------------------------
template<bool CONV_A>
__device__ __forceinline__ void gemm_body(
    const float* __restrict__ X, const float* __restrict__ W,
    const float* __restrict__ rmask, float* __restrict__ Y, int round_out,
    int row0, int col0)
{
    extern __shared__ float gsm[];
    float* Xs = gsm;                 // [2][128*36]
    float* Ws = gsm + 2 * 128 * 36;  // [2][128*36]

    const int tid  = threadIdx.x;
    const int lane = tid & 31;
    const int wid  = tid >> 5;
    const int g    = lane >> 2;
    const int tg   = lane & 3;
    const int wm   = wid >> 2;
    const int wn   = wid & 3;

    const int lr = tid >> 3;
    const int lc = (tid & 7) << 2;

    const uint32_t aoff = (((wm << 6) + (lane & 15)) * 36 + ((lane >> 4) << 2)) << 2;
    const uint32_t boff = (((wn << 5) + (lane & 7) + ((lane & 16) >> 1)) * 36
                           + ((lane & 8) >> 1)) << 2;
    const uint32_t xsBase = smem_u32(Xs);
    const uint32_t wsBase = smem_u32(Ws);

    float c[4][4][4];
#pragma unroll
    for (int mi = 0; mi < 4; mi++)
#pragma unroll
        for (int nj = 0; nj < 4; nj++)
#pragma unroll
            for (int q = 0; q < 4; q++) c[mi][nj][q] = 0.0f;

#pragma unroll
    for (int t = 0; t < 4; t++) {
        const int r = lr + (t << 5);
        cp16(smem_u32(&Xs[r * 36 + lc]), X + (size_t)(row0 + r) * DM + lc);
        cp16(smem_u32(&Ws[r * 36 + lc]), W + (size_t)(col0 + r) * DM + lc);
    }
    cp_commit();

    for (int kt = 0; kt < 16; kt++) {
        const int cur = kt & 1;
        cp_wait0();
        __syncthreads();
        if (kt + 1 < 16) {
            const int nb = cur ^ 1;
            const int k0 = (kt + 1) << 5;
#pragma unroll
            for (int t = 0; t < 4; t++) {
                const int r = lr + (t << 5);
                cp16(smem_u32(&Xs[nb * 128 * 36 + r * 36 + lc]),
                     X + (size_t)(row0 + r) * DM + k0 + lc);
                cp16(smem_u32(&Ws[nb * 128 * 36 + r * 36 + lc]),
                     W + (size_t)(col0 + r) * DM + k0 + lc);
            }
            cp_commit();
        }

        const uint32_t xb = xsBase + ((cur * 128 * 36) << 2) + aoff;
        const uint32_t wb = wsBase + ((cur * 128 * 36) << 2) + boff;
#pragma unroll
        for (int kk = 0; kk < 4; kk++) {
            const int kbb = (kk << 3) << 2;
            uint32_t a[4][4], b[2][4];
#pragma unroll
            for (int mi = 0; mi < 4; mi++) {
                ldsm4(a[mi], xb + mi * (16 * 36 * 4) + kbb);
                if (CONV_A) {
#pragma unroll
                    for (int q = 0; q < 4; q++)
                        a[mi][q] = f2tf(__uint_as_float(a[mi][q]));
                }
            }
#pragma unroll
            for (int njp = 0; njp < 2; njp++)
                ldsm4(b[njp], wb + njp * (16 * 36 * 4) + kbb);
#pragma unroll
            for (int mi = 0; mi < 4; mi++) {
                mma_tf32(c[mi][0], a[mi], b[0]);
                mma_tf32(c[mi][1], a[mi], b[0] + 2);
                mma_tf32(c[mi][2], a[mi], b[1]);
                mma_tf32(c[mi][3], a[mi], b[1] + 2);
            }
        }
        __syncthreads();
    }

#pragma unroll
    for (int mi = 0; mi < 4; mi++) {
        const int r1 = row0 + (wm << 6) + (mi << 4) + g;
        const int r2 = r1 + 8;
        const float m1 = rmask[r1];
        const float m2 = rmask[r2];
#pragma unroll
        for (int nj = 0; nj < 4; nj++) {
            const int cc = col0 + (wn << 5) + (nj << 3) + (tg << 1);
            float v[4];
            v[0] = m1 * c[mi][nj][0]; v[1] = m1 * c[mi][nj][1];
            v[2] = m2 * c[mi][nj][2]; v[3] = m2 * c[mi][nj][3];
            if (round_out) {
#pragma unroll
                for (int q = 0; q < 4; q++) v[q] = __uint_as_float(f2tf(v[q]));
            }
            float2 v1; v1.x = v[0]; v1.y = v[1];
            float2 v2; v2.x = v[2]; v2.y = v[3];
            *(float2*)(Y + (size_t)r1 * DM + cc) = v1;
            *(float2*)(Y + (size_t)r2 * DM + cc) = v2;
        }
    }
}

// Fused Q/K/V projections (raw X -> A cvt needed; W pre-rounded).
__global__ __launch_bounds__(256, 2) void gemm_qkv(
    const float* __restrict__ Qin, const float* __restrict__ Kin,
    const float* __restrict__ Vin,
    const float* __restrict__ qm, const float* __restrict__ km)
{
    const float* X; const float* W; const float* msk; float* Y;
    if (blockIdx.z == 0)      { X = Qin; W = g_W;               msk = qm; Y = g_Qp; }
    else if (blockIdx.z == 1) { X = Kin; W = g_W + DM * DM;     msk = km; Y = g_Kp; }
    else                      { X = Vin; W = g_W + 2 * DM * DM; msk = km; Y = g_Vp; }
    gemm_body<true>(X, W, msk, Y, 1, blockIdx.y << 7, blockIdx.x << 7);
}

// WO projection: X = g_Y (already tf32-rounded by attention), W pre-rounded.
__global__ __launch_bounds__(256, 2) void gemm_out(
    const float* __restrict__ rmask, float* __restrict__ Y)
{
    gemm_body<false>(g_Y, g_W + 3 * DM * DM, rmask, Y, 0,
                     blockIdx.y << 7, blockIdx.x << 7);
}

// ---------------------------------------------------------------------------
// TF32 flash attention, no-max softmax (R14 structure: prefetch at iter top,
// full-iteration prefetch distance). NEW: S and exp/P-store fused at njp
// granularity — each 16-wide n-group's exp/pack overlaps the next group's
// independent MMAs. Per-element math and accumulation order unchanged.
// 128 threads = 4 warps x 32 query rows, 2 CTAs/SM.
// Smem: PQs[128][76] (Q then P) + Ks[2][64][68] + Vs[2][64][68] = 108544 B.
// ---------------------------------------------------------------------------
__global__ __launch_bounds__(128, 2) void attn_tf32(const float* __restrict__ k_mas)
{
    extern __shared__ float smf[];
    float* PQs = smf;                                  // [128][76]  Q then P
    float* Ks  = smf + 128 * 76;                       // [2][64][68]
    float* Vs  = smf + 128 * 76 + 2 * 64 * 68;         // [2][64][68]

    const int tid  = threadIdx.x;
    const int lane = tid & 31;
    const int wid  = tid >> 5;        // 0..3
    const int g    = lane >> 2;
    const int tg   = lane & 3;
    const int q0   = blockIdx.x << 7;
    const int h    = blockIdx.y;
    const int b    = blockIdx.z;
    const int qrow = wid << 5;        // 32 query rows per warp

    const float NEGINF = neg_inf_f();

    uint32_t pqA[2];
#pragma unroll
    for (int mi = 0; mi < 2; mi++)
        pqA[mi] = smem_u32(PQs) +
            (((qrow + (mi << 4) + (lane & 15)) * 76 + ((lane >> 4) << 2)) << 2);
    const uint32_t ksB0 = smem_u32(Ks) +
        (((((lane & 7) + ((lane & 16) >> 1)) * 68) + ((lane & 8) >> 1)) << 2);

    const int lr = tid >> 4;          // 0..7
    const int lc = (tid & 15) << 2;   // 0..60

    // prologue: Q tile into PQs (group 0), then K/V tile 0 (group 1)
    {
        const float* Qb = g_Qp + ((size_t)b * SEQ + q0) * DM + h * DKH;
#pragma unroll
        for (int t = 0; t < 16; t++) {
            const int r = lr + (t << 3);
            cp16(smem_u32(&PQs[r * 76 + lc]), Qb + (size_t)r * DM + lc);
        }
        cp_commit();
        const float* Kb = g_Kp + ((size_t)b * SEQ) * DM + h * DKH;
        const float* Vb = g_Vp + ((size_t)b * SEQ) * DM + h * DKH;
#pragma unroll
        for (int t = 0; t < 8; t++) {
            const int r = lr + (t << 3);
            cp16(smem_u32(&Ks[r * 68 + lc]), Kb + (size_t)r * DM + lc);
            cp16(smem_u32(&Vs[r * 68 + lc]), Vb + (size_t)r * DM + lc);
        }
        cp_commit();
    }

    // wait for Q only, hoist Q fragments to registers; PQs then becomes P space.
    cp_wait1();
    __syncthreads();
    uint32_t qf[2][8][4];
#pragma unroll
    for (int mi = 0; mi < 2; mi++)
#pragma unroll
        for (int kk = 0; kk < 8; kk++)
            ldsm4(qf[mi][kk], pqA[mi] + ((kk << 3) << 2));

    float o[2][8][4];
#pragma unroll
    for (int mi = 0; mi < 2; mi++)
#pragma unroll
        for (int dj = 0; dj < 8; dj++)
#pragma unroll
            for (int q = 0; q < 4; q++) o[mi][dj][q] = 0.0f;
    float lrow[2][2];
#pragma unroll
    for (int mi = 0; mi < 2; mi++) { lrow[mi][0] = 0.0f; lrow[mi][1] = 0.0f; }

    int qr[2][2];
#pragma unroll
    for (int mi = 0; mi < 2; mi++) {
        qr[mi][0] = q0 + qrow + (mi << 4) + g;
        qr[mi][1] = qr[mi][0] + 8;
    }

    for (int kt = 0; kt < SEQ / 64; kt++) {
        const int cur = kt & 1;
        cp_wait0();
        __syncthreads();

        if (kt + 1 < SEQ / 64) {
            const int nb = cur ^ 1;
            const int kk1 = (kt + 1) << 6;
            const float* Kb = g_Kp + ((size_t)b * SEQ + kk1) * DM + h * DKH;
            const float* Vb = g_Vp + ((size_t)b * SEQ + kk1) * DM + h * DKH;
#pragma unroll
            for (int t = 0; t < 8; t++) {
                const int r = lr + (t << 3);
                cp16(smem_u32(&Ks[(nb * 64 + r) * 68 + lc]), Kb + (size_t)r * DM + lc);
                cp16(smem_u32(&Vs[(nb * 64 + r) * 68 + lc]), Vb + (size_t)r * DM + lc);
            }
            cp_commit();
        }

        uint2 mw[2][2];
#pragma unroll
        for (int mi = 0; mi < 2; mi++) {
            mw[mi][0] = *(const uint2*)(g_mask + ((size_t)b * SEQ + qr[mi][0]) * MWORDS + (kt << 1));
            mw[mi][1] = *(const uint2*)(g_mask + ((size_t)b * SEQ + qr[mi][1]) * MWORDS + (kt << 1));
        }

        // Fused S + softmax: per 16-wide n-group, MMAs then exp/pack/store.
        // Group njp+1's MMAs are independent of group njp's exp -> overlap.
        const uint32_t ksB = ksB0 + ((cur * 64 * 68) << 2);
#pragma unroll
        for (int njp = 0; njp < 4; njp++) {
            float s[2][2][4];
#pragma unroll
            for (int mi = 0; mi < 2; mi++)
#pragma unroll
                for (int u = 0; u < 2; u++)
#pragma unroll
                    for (int q = 0; q < 4; q++) s[mi][u][q] = 0.0f;

#pragma unroll
            for (int kk = 0; kk < 8; kk++) {
                const int kb = kk << 3;
                uint32_t bb[4];
                ldsm4(bb, ksB + ((njp * 16 * 68 + kb) << 2));
                mma_tf32(s[0][0], qf[0][kk], bb);
                mma_tf32(s[0][1], qf[0][kk], bb + 2);
                mma_tf32(s[1][0], qf[1][kk], bb);
                mma_tf32(s[1][1], qf[1][kk], bb + 2);
            }

#pragma unroll
            for (int mi = 0; mi < 2; mi++) {
#pragma unroll
                for (int u = 0; u < 2; u++) {
                    const int nj = (njp << 1) + u;
                    const int j0 = (nj << 3) + (tg << 1);
                    const uint32_t w1 = (j0 & 32) ? mw[mi][0].y : mw[mi][0].x;
                    const uint32_t w2 = (j0 & 32) ? mw[mi][1].y : mw[mi][1].x;
                    const int bi = j0 & 31;
                    const float p0 = __expf(((w1 >> bi) & 1u)       ? s[mi][u][0] * 0.125f : NEGINF);
                    const float p1 = __expf(((w1 >> (bi + 1)) & 1u) ? s[mi][u][1] * 0.125f : NEGINF);
                    const float p2 = __expf(((w2 >> bi) & 1u)       ? s[mi][u][2] * 0.125f : NEGINF);
                    const float p3 = __expf(((w2 >> (bi + 1)) & 1u) ? s[mi][u][3] * 0.125f : NEGINF);
                    lrow[mi][0] += p0 + p1;
                    lrow[mi][1] += p2 + p3;
                    const int pc = (nj << 3) + (tg << 1);
                    uint2 u1; u1.x = f2tf(p0); u1.y = f2tf(p1);
                    uint2 u2; u2.x = f2tf(p2); u2.y = f2tf(p3);
                    *(uint2*)&PQs[(qrow + (mi << 4) + g    ) * 76 + pc] = u1;
                    *(uint2*)&PQs[(qrow + (mi << 4) + 8 + g) * 76 + pc] = u2;
                }
            }
        }
        __syncwarp();   // P stores visible within warp before LDSM A reads

        // O += P @ V : P via LDSM from PQs, V fragments shared across m-tiles
        const float* Vb = Vs + cur * 64 * 68;
#pragma unroll
        for (int kk = 0; kk < 8; kk++) {
            const int kb = kk << 3;
            uint32_t a[2][4];
            ldsm4(a[0], pqA[0] + (kb << 2));
            ldsm4(a[1], pqA[1] + (kb << 2));
#pragma unroll
            for (int dj = 0; dj < 8; dj++) {
                uint32_t bb[2];
                bb[0] = __float_as_uint(Vb[(kb + tg    ) * 68 + (dj << 3) + g]);
                bb[1] = __float_as_uint(Vb[(kb + tg + 4) * 68 + (dj << 3) + g]);
                mma_tf32(o[0][dj], a[0], bb);
                mma_tf32(o[1][dj], a[1], bb);
            }
        }
    }

    // Epilogue: quad-reduce deferred row sums, normalize, post-mask,
    // tf32-round for the WO GEMM.
#pragma unroll
    for (int mi = 0; mi < 2; mi++) {
        float l0 = lrow[mi][0], l1 = lrow[mi][1];
        l0 += __shfl_xor_sync(0xffffffffu, l0, 1);
        l0 += __shfl_xor_sync(0xffffffffu, l0, 2);
        l1 += __shfl_xor_sync(0xffffffffu, l1, 1);
        l1 += __shfl_xor_sync(0xffffffffu, l1, 2);
        const float sc0 = k_mas[(size_t)b * SEQ + qr[mi][0]] / l0;
        const float sc1 = k_mas[(size_t)b * SEQ + qr[mi][1]] / l1;
        float* Y1 = g_Y + ((size_t)b * SEQ + qr[mi][0]) * DM + h * DKH;
        float* Y2 = g_Y + ((size_t)b * SEQ + qr[mi][1]) * DM + h * DKH;
#pragma unroll
        for (int dj = 0; dj < 8; dj++) {
            const int cc = (dj << 3) + (tg << 1);
            float2 v1, v2;
            v1.x = __uint_as_float(f2tf(o[mi][dj][0] * sc0));
            v1.y = __uint_as_float(f2tf(o[mi][dj][1] * sc0));
            v2.x = __uint_as_float(f2tf(o[mi][dj][2] * sc1));
            v2.y = __uint_as_float(f2tf(o[mi][dj][3] * sc1));
            *(float2*)(Y1 + cc) = v1;
            *(float2*)(Y2 + cc) = v2;
        }
    }
}

// ---------------------------------------------------------------------------
extern "C" void kernel_launch(void* const* d_in, const int* in_sizes, int n_in,
                              void* d_out, int out_size)
{
    (void)in_sizes; (void)n_in; (void)out_size;
    const float* Q   = (const float*)d_in[0];
    const float* K   = (const float*)d_in[1];
    const float* V   = (const float*)d_in[2];
    const float* qm  = (const float*)d_in[3];
    const float* km  = (const float*)d_in[4];
    const float* am  = (const float*)d_in[5];
    const float* WQ  = (const float*)d_in[6];
    const float* WK  = (const float*)d_in[7];
    const float* WV  = (const float*)d_in[8];
    const float* WO  = (const float*)d_in[9];
    float* out = (float*)d_out;

    const int gemm_smem = 2 * 2 * 128 * 36 * (int)sizeof(float);   // 73728
    cudaFuncSetAttribute(gemm_qkv,
                         cudaFuncAttributeMaxDynamicSharedMemorySize, gemm_smem);
    cudaFuncSetAttribute(gemm_out,
                         cudaFuncAttributeMaxDynamicSharedMemorySize, gemm_smem);

    round_w<<<dim3(DM * DM / 4 / 256, 4), 256>>>(WQ, WK, WV, WO);
    pack_mask<<<(BSZ * SEQ * SEQ) / 1024, 256>>>(am);

    gemm_qkv<<<dim3(DM / 128, MR / 128, 3), 256, gemm_smem>>>(Q, K, V, qm, km);

    const int attn_smem = (128 * 76 + 2 * 64 * 68 + 2 * 64 * 68)
                          * (int)sizeof(float);  // 108544
    cudaFuncSetAttribute(attn_tf32, cudaFuncAttributeMaxDynamicSharedMemorySize,
                         attn_smem);
    attn_tf32<<<dim3(SEQ / 128, NH, BSZ), 128, attn_smem>>>(km);

    gemm_out<<<dim3(DM / 128, MR / 128), 256, gemm_smem>>>(km, out);
}

// round 17
// speedup vs baseline: 1.8000x; 1.0266x over previous
#include <cuda_runtime.h>
#include <cstdint>

#define BSZ 4
#define SEQ 2048
#define DM  512
#define NH  8
#define DKH 64
#define MR  (BSZ * SEQ)   // 8192 flattened rows
#define MWORDS (SEQ / 32) // 64 mask words per row

// Scratch (allocation-free rule: __device__ globals)
__device__ float    g_Qp[(size_t)MR * DM];
__device__ float    g_Kp[(size_t)MR * DM];
__device__ float    g_Vp[(size_t)MR * DM];
__device__ float    g_Y [(size_t)MR * DM];
__device__ float    g_W [(size_t)4 * DM * DM];   // tf32-rounded WQ|WK|WV|WO
__device__ uint32_t g_mask[(size_t)BSZ * SEQ * MWORDS];

__device__ __forceinline__ float neg_inf_f() { return __int_as_float(0xff800000u); }

__device__ __forceinline__ uint32_t f2tf(float f) {
    uint32_t u;
    asm("cvt.rna.tf32.f32 %0, %1;" : "=r"(u) : "f"(f));
    return u;
}

__device__ __forceinline__ void mma_tf32(float* c, const uint32_t* a, const uint32_t* b) {
    asm volatile(
        "mma.sync.aligned.m16n8k8.row.col.f32.tf32.tf32.f32 "
        "{%0,%1,%2,%3}, {%4,%5,%6,%7}, {%8,%9}, {%0,%1,%2,%3};\n"
        : "+f"(c[0]), "+f"(c[1]), "+f"(c[2]), "+f"(c[3])
        : "r"(a[0]), "r"(a[1]), "r"(a[2]), "r"(a[3]), "r"(b[0]), "r"(b[1]));
}

__device__ __forceinline__ void ldsm4(uint32_t* r, uint32_t addr) {
    asm volatile("ldmatrix.sync.aligned.m8n8.x4.shared.b16 {%0,%1,%2,%3}, [%4];"
        : "=r"(r[0]), "=r"(r[1]), "=r"(r[2]), "=r"(r[3]) : "r"(addr));
}

__device__ __forceinline__ uint32_t smem_u32(const void* p) {
    return (uint32_t)__cvta_generic_to_shared(p);
}

__device__ __forceinline__ void cp16(uint32_t dst, const void* src) {
    asm volatile("cp.async.cg.shared.global [%0], [%1], 16;\n"
        :: "r"(dst), "l"(src) : "memory");
}
__device__ __forceinline__ void cp_commit() {
    asm volatile("cp.async.commit_group;\n" ::: "memory");
}
__device__ __forceinline__ void cp_wait0() {
    asm volatile("cp.async.wait_group 0;\n" ::: "memory");
}
__device__ __forceinline__ void cp_wait1() {
    asm volatile("cp.async.wait_group 1;\n" ::: "memory");
}

// ---------------------------------------------------------------------------
// Prologue: tf32-round the four weight matrices into g_W.
// ---------------------------------------------------------------------------
__global__ __launch_bounds__(256) void round_w(
    const float* __restrict__ WQ, const float* __restrict__ WK,
    const float* __restrict__ WV, const float* __restrict__ WO)
{
    const int idx = blockIdx.x * 256 + threadIdx.x;       // float4 index
    const float* src = (blockIdx.y == 0) ? WQ : (blockIdx.y == 1) ? WK
                     : (blockIdx.y == 2) ? WV : WO;
    float4 v = ((const float4*)src)[idx];
    uint4 u;
    u.x = f2tf(v.x); u.y = f2tf(v.y); u.z = f2tf(v.z); u.w = f2tf(v.w);
    ((uint4*)(g_W + (size_t)blockIdx.y * DM * DM))[idx] = u;
}

// ---------------------------------------------------------------------------
// Pack att_mas (0.0/1.0 floats) into bits.
// ---------------------------------------------------------------------------
__global__ __launch_bounds__(256) void pack_mask(const float* __restrict__ am)
{
    const int lane = threadIdx.x & 31;
    const size_t wg = (size_t)blockIdx.x * 8 + (threadIdx.x >> 5);
    const size_t base = wg * 128;
    const float v0 = am[base + lane];
    const float v1 = am[base + 32 + lane];
    const float v2 = am[base + 64 + lane];
    const float v3 = am[base + 96 + lane];
    const unsigned b0 = __ballot_sync(0xffffffffu, v0 != 0.0f);
    const unsigned b1 = __ballot_sync(0xffffffffu, v1 != 0.0f);
    const unsigned b2 = __ballot_sync(0xffffffffu, v2 != 0.0f);
    const unsigned b3 = __ballot_sync(0xffffffffu, v3 != 0.0f);
    if (lane < 4) {
        unsigned w = (lane == 0) ? b0 : (lane == 1) ? b1 : (lane == 2) ? b2 : b3;
        g_mask[wg * 4 + lane] = w;
    }
}

// ---------------------------------------------------------------------------
// SIMT tf32 GEMM body (R7, proven): pre-rounded W (no B cvt),
// ldmatrix fragments, cp.async double-buffered k-tiles.
// Block 128x128x32, 8 warps (2x4), warp tile 64x32.
// ---------------------------------------------------------------------------
template<bool CONV_A>
__device__ __forceinline__ void gemm_body(
    const float* __restrict__ X, const float* __restrict__ W,
    const float* __restrict__ rmask, float* __restrict__ Y, int round_out,
    int row0, int col0)
{
    extern __shared__ float gsm[];
    float* Xs = gsm;                 // [2][128*36]
    float* Ws = gsm + 2 * 128 * 36;  // [2][128*36]

    const int tid  = threadIdx.x;
    const int lane = tid & 31;
    const int wid  = tid >> 5;
    const int g    = lane >> 2;
    const int tg   = lane & 3;
    const int wm   = wid >> 2;
    const int wn   = wid & 3;

    const int lr = tid >> 3;
    const int lc = (tid & 7) << 2;

    const uint32_t aoff = (((wm << 6) + (lane & 15)) * 36 + ((lane >> 4) << 2)) << 2;
    const uint32_t boff = (((wn << 5) + (lane & 7) + ((lane & 16) >> 1)) * 36
                           + ((lane & 8) >> 1)) << 2;
    const uint32_t xsBase = smem_u32(Xs);
    const uint32_t wsBase = smem_u32(Ws);

    float c[4][4][4];
#pragma unroll
    for (int mi = 0; mi < 4; mi++)
#pragma unroll
        for (int nj = 0; nj < 4; nj++)
#pragma unroll
            for (int q = 0; q < 4; q++) c[mi][nj][q] = 0.0f;

#pragma unroll
    for (int t = 0; t < 4; t++) {
        const int r = lr + (t << 5);
        cp16(smem_u32(&Xs[r * 36 + lc]), X + (size_t)(row0 + r) * DM + lc);
        cp16(smem_u32(&Ws[r * 36 + lc]), W + (size_t)(col0 + r) * DM + lc);
    }
    cp_commit();

    for (int kt = 0; kt < 16; kt++) {
        const int cur = kt & 1;
        cp_wait0();
        __syncthreads();
        if (kt + 1 < 16) {
            const int nb = cur ^ 1;
            const int k0 = (kt + 1) << 5;
#pragma unroll
            for (int t = 0; t < 4; t++) {
                const int r = lr + (t << 5);
                cp16(smem_u32(&Xs[nb * 128 * 36 + r * 36 + lc]),
                     X + (size_t)(row0 + r) * DM + k0 + lc);
                cp16(smem_u32(&Ws[nb * 128 * 36 + r * 36 + lc]),
                     W + (size_t)(col0 + r) * DM + k0 + lc);
            }
            cp_commit();
        }

        const uint32_t xb = xsBase + ((cur * 128 * 36) << 2) + aoff;
        const uint32_t wb = wsBase + ((cur * 128 * 36) << 2) + boff;
#pragma unroll
        for (int kk = 0; kk < 4; kk++) {
            const int kbb = (kk << 3) << 2;
            uint32_t a[4][4], b[2][4];
#pragma unroll
            for (int mi = 0; mi < 4; mi++) {
                ldsm4(a[mi], xb + mi * (16 * 36 * 4) + kbb);
                if (CONV_A) {
#pragma unroll
                    for (int q = 0; q < 4; q++)
                        a[mi][q] = f2tf(__uint_as_float(a[mi][q]));
                }
            }
#pragma unroll
            for (int njp = 0; njp < 2; njp++)
                ldsm4(b[njp], wb + njp * (16 * 36 * 4) + kbb);
#pragma unroll
            for (int mi = 0; mi < 4; mi++) {
                mma_tf32(c[mi][0], a[mi], b[0]);
                mma_tf32(c[mi][1], a[mi], b[0] + 2);
                mma_tf32(c[mi][2], a[mi], b[1]);
                mma_tf32(c[mi][3], a[mi], b[1] + 2);
            }
        }
        __syncthreads();
    }

#pragma unroll
    for (int mi = 0; mi < 4; mi++) {
        const int r1 = row0 + (wm << 6) + (mi << 4) + g;
        const int r2 = r1 + 8;
        const float m1 = rmask[r1];
        const float m2 = rmask[r2];
#pragma unroll
        for (int nj = 0; nj < 4; nj++) {
            const int cc = col0 + (wn << 5) + (nj << 3) + (tg << 1);
            float v[4];
            v[0] = m1 * c[mi][nj][0]; v[1] = m1 * c[mi][nj][1];
            v[2] = m2 * c[mi][nj][2]; v[3] = m2 * c[mi][nj][3];
            if (round_out) {
#pragma unroll
                for (int q = 0; q < 4; q++) v[q] = __uint_as_float(f2tf(v[q]));
            }
            float2 v1; v1.x = v[0]; v1.y = v[1];
            float2 v2; v2.x = v[2]; v2.y = v[3];
            *(float2*)(Y + (size_t)r1 * DM + cc) = v1;
            *(float2*)(Y + (size_t)r2 * DM + cc) = v2;
        }
    }
}

// Fused Q/K/V projections (raw X -> A cvt needed; W pre-rounded).
__global__ __launch_bounds__(256, 2) void gemm_qkv(
    const float* __restrict__ Qin, const float* __restrict__ Kin,
    const float* __restrict__ Vin,
    const float* __restrict__ qm, const float* __restrict__ km)
{
    const float* X; const float* W; const float* msk; float* Y;
    if (blockIdx.z == 0)      { X = Qin; W = g_W;               msk = qm; Y = g_Qp; }
    else if (blockIdx.z == 1) { X = Kin; W = g_W + DM * DM;     msk = km; Y = g_Kp; }
    else                      { X = Vin; W = g_W + 2 * DM * DM; msk = km; Y = g_Vp; }
    gemm_body<true>(X, W, msk, Y, 1, blockIdx.y << 7, blockIdx.x << 7);
}

// WO projection: X = g_Y (already tf32-rounded by attention), W pre-rounded.
__global__ __launch_bounds__(256, 2) void gemm_out(
    const float* __restrict__ rmask, float* __restrict__ Y)
{
    gemm_body<false>(g_Y, g_W + 3 * DM * DM, rmask, Y, 0,
                     blockIdx.y << 7, blockIdx.x << 7);
}

// ---------------------------------------------------------------------------
// TF32 flash attention, no-max softmax, njp-fused S/exp (R16 structure).
// CHANGE: V smem pitch 68 -> 72 (72 % 32 == 8 => bank = 8*tg + g covers all
// 32 banks exactly once => the 128 scalar V loads per thread per kt become
// conflict-free, halving their L1 wavefront cost).
// 128 threads = 4 warps x 32 query rows, 2 CTAs/SM.
// Smem: PQs[128][76] + Ks[2][64][68] + Vs[2][64][72] = 110592 B.
// ---------------------------------------------------------------------------
__global__ __launch_bounds__(128, 2) void attn_tf32(const float* __restrict__ k_mas)
{
    extern __shared__ float smf[];
    float* PQs = smf;                                  // [128][76]  Q then P
    float* Ks  = smf + 128 * 76;                       // [2][64][68]
    float* Vs  = smf + 128 * 76 + 2 * 64 * 68;         // [2][64][72]

    const int tid  = threadIdx.x;
    const int lane = tid & 31;
    const int wid  = tid >> 5;        // 0..3
    const int g    = lane >> 2;
    const int tg   = lane & 3;
    const int q0   = blockIdx.x << 7;
    const int h    = blockIdx.y;
    const int b    = blockIdx.z;
    const int qrow = wid << 5;        // 32 query rows per warp

    const float NEGINF = neg_inf_f();

    uint32_t pqA[2];
#pragma unroll
    for (int mi = 0; mi < 2; mi++)
        pqA[mi] = smem_u32(PQs) +
            (((qrow + (mi << 4) + (lane & 15)) * 76 + ((lane >> 4) << 2)) << 2);
    const uint32_t ksB0 = smem_u32(Ks) +
        (((((lane & 7) + ((lane & 16) >> 1)) * 68) + ((lane & 8) >> 1)) << 2);

    const int lr = tid >> 4;          // 0..7
    const int lc = (tid & 15) << 2;   // 0..60

    // prologue: Q tile into PQs (group 0), then K/V tile 0 (group 1)
    {
        const float* Qb = g_Qp + ((size_t)b * SEQ + q0) * DM + h * DKH;
#pragma unroll
        for (int t = 0; t < 16; t++) {
            const int r = lr + (t << 3);
            cp16(smem_u32(&PQs[r * 76 + lc]), Qb + (size_t)r * DM + lc);
        }
        cp_commit();
        const float* Kb = g_Kp + ((size_t)b * SEQ) * DM + h * DKH;
        const float* Vb = g_Vp + ((size_t)b * SEQ) * DM + h * DKH;
#pragma unroll
        for (int t = 0; t < 8; t++) {
            const int r = lr + (t << 3);
            cp16(smem_u32(&Ks[r * 68 + lc]), Kb + (size_t)r * DM + lc);
            cp16(smem_u32(&Vs[r * 72 + lc]), Vb + (size_t)r * DM + lc);
        }
        cp_commit();
    }

    // wait for Q only, hoist Q fragments to registers; PQs then becomes P space.
    cp_wait1();
    __syncthreads();
    uint32_t qf[2][8][4];
#pragma unroll
    for (int mi = 0; mi < 2; mi++)
#pragma unroll
        for (int kk = 0; kk < 8; kk++)
            ldsm4(qf[mi][kk], pqA[mi] + ((kk << 3) << 2));

    float o[2][8][4];
#pragma unroll
    for (int mi = 0; mi < 2; mi++)
#pragma unroll
        for (int dj = 0; dj < 8; dj++)
#pragma unroll
            for (int q = 0; q < 4; q++) o[mi][dj][q] = 0.0f;
    float lrow[2][2];
#pragma unroll
    for (int mi = 0; mi < 2; mi++) { lrow[mi][0] = 0.0f; lrow[mi][1] = 0.0f; }

    int qr[2][2];
#pragma unroll
    for (int mi = 0; mi < 2; mi++) {
        qr[mi][0] = q0 + qrow + (mi << 4) + g;
        qr[mi][1] = qr[mi][0] + 8;
    }

    for (int kt = 0; kt < SEQ / 64; kt++) {
        const int cur = kt & 1;
        cp_wait0();
        __syncthreads();

        if (kt + 1 < SEQ / 64) {
            const int nb = cur ^ 1;
            const int kk1 = (kt + 1) << 6;
            const float* Kb = g_Kp + ((size_t)b * SEQ + kk1) * DM + h * DKH;
            const float* Vb = g_Vp + ((size_t)b * SEQ + kk1) * DM + h * DKH;
#pragma unroll
            for (int t = 0; t < 8; t++) {
                const int r = lr + (t << 3);
                cp16(smem_u32(&Ks[(nb * 64 + r) * 68 + lc]), Kb + (size_t)r * DM + lc);
                cp16(smem_u32(&Vs[(nb * 64 + r) * 72 + lc]), Vb + (size_t)r * DM + lc);
            }
            cp_commit();
        }

        uint2 mw[2][2];
#pragma unroll
        for (int mi = 0; mi < 2; mi++) {
            mw[mi][0] = *(const uint2*)(g_mask + ((size_t)b * SEQ + qr[mi][0]) * MWORDS + (kt << 1));
            mw[mi][1] = *(const uint2*)(g_mask + ((size_t)b * SEQ + qr[mi][1]) * MWORDS + (kt << 1));
        }

        // Fused S + softmax: per 16-wide n-group, MMAs then exp/pack/store.
        const uint32_t ksB = ksB0 + ((cur * 64 * 68) << 2);
#pragma unroll
        for (int njp = 0; njp < 4; njp++) {
            float s[2][2][4];
#pragma unroll
            for (int mi = 0; mi < 2; mi++)
#pragma unroll
                for (int u = 0; u < 2; u++)
#pragma unroll
                    for (int q = 0; q < 4; q++) s[mi][u][q] = 0.0f;

#pragma unroll
            for (int kk = 0; kk < 8; kk++) {
                const int kb = kk << 3;
                uint32_t bb[4];
                ldsm4(bb, ksB + ((njp * 16 * 68 + kb) << 2));
                mma_tf32(s[0][0], qf[0][kk], bb);
                mma_tf32(s[0][1], qf[0][kk], bb + 2);
                mma_tf32(s[1][0], qf[1][kk], bb);
                mma_tf32(s[1][1], qf[1][kk], bb + 2);
            }

#pragma unroll
            for (int mi = 0; mi < 2; mi++) {
#pragma unroll
                for (int u = 0; u < 2; u++) {
                    const int nj = (njp << 1) + u;
                    const int j0 = (nj << 3) + (tg << 1);
                    const uint32_t w1 = (j0 & 32) ? mw[mi][0].y : mw[mi][0].x;
                    const uint32_t w2 = (j0 & 32) ? mw[mi][1].y : mw[mi][1].x;
                    const int bi = j0 & 31;
                    const float p0 = __expf(((w1 >> bi) & 1u)       ? s[mi][u][0] * 0.125f : NEGINF);
                    const float p1 = __expf(((w1 >> (bi + 1)) & 1u) ? s[mi][u][1] * 0.125f : NEGINF);
                    const float p2 = __expf(((w2 >> bi) & 1u)       ? s[mi][u][2] * 0.125f : NEGINF);
                    const float p3 = __expf(((w2 >> (bi + 1)) & 1u) ? s[mi][u][3] * 0.125f : NEGINF);
                    lrow[mi][0] += p0 + p1;
                    lrow[mi][1] += p2 + p3;
                    const int pc = (nj << 3) + (tg << 1);
                    uint2 u1; u1.x = f2tf(p0); u1.y = f2tf(p1);
                    uint2 u2; u2.x = f2tf(p2); u2.y = f2tf(p3);
                    *(uint2*)&PQs[(qrow + (mi << 4) + g    ) * 76 + pc] = u1;
                    *(uint2*)&PQs[(qrow + (mi << 4) + 8 + g) * 76 + pc] = u2;
                }
            }
        }
        __syncwarp();   // P stores visible within warp before LDSM A reads

        // O += P @ V : P via LDSM from PQs, V scalar loads (now conflict-free)
        const float* Vb = Vs + cur * 64 * 72;
#pragma unroll
        for (int kk = 0; kk < 8; kk++) {
            const int kb = kk << 3;
            uint32_t a[2][4];
            ldsm4(a[0], pqA[0] + (kb << 2));
            ldsm4(a[1], pqA[1] + (kb << 2));
#pragma unroll
            for (int dj = 0; dj < 8; dj++) {
                uint32_t bb[2];
                bb[0] = __float_as_uint(Vb[(kb + tg    ) * 72 + (dj << 3) + g]);
                bb[1] = __float_as_uint(Vb[(kb + tg + 4) * 72 + (dj << 3) + g]);
                mma_tf32(o[0][dj], a[0], bb);
                mma_tf32(o[1][dj], a[1], bb);
            }
        }
    }

    // Epilogue: quad-reduce deferred row sums, normalize, post-mask,
    // tf32-round for the WO GEMM.
#pragma unroll
    for (int mi = 0; mi < 2; mi++) {
        float l0 = lrow[mi][0], l1 = lrow[mi][1];
        l0 += __shfl_xor_sync(0xffffffffu, l0, 1);
        l0 += __shfl_xor_sync(0xffffffffu, l0, 2);
        l1 += __shfl_xor_sync(0xffffffffu, l1, 1);
        l1 += __shfl_xor_sync(0xffffffffu, l1, 2);
        const float sc0 = k_mas[(size_t)b * SEQ + qr[mi][0]] / l0;
        const float sc1 = k_mas[(size_t)b * SEQ + qr[mi][1]] / l1;
        float* Y1 = g_Y + ((size_t)b * SEQ + qr[mi][0]) * DM + h * DKH;
        float* Y2 = g_Y + ((size_t)b * SEQ + qr[mi][1]) * DM + h * DKH;
#pragma unroll
        for (int dj = 0; dj < 8; dj++) {
            const int cc = (dj << 3) + (tg << 1);
            float2 v1, v2;
            v1.x = __uint_as_float(f2tf(o[mi][dj][0] * sc0));
            v1.y = __uint_as_float(f2tf(o[mi][dj][1] * sc0));
            v2.x = __uint_as_float(f2tf(o[mi][dj][2] * sc1));
            v2.y = __uint_as_float(f2tf(o[mi][dj][3] * sc1));
            *(float2*)(Y1 + cc) = v1;
            *(float2*)(Y2 + cc) = v2;
        }
    }
}

// ---------------------------------------------------------------------------
extern "C" void kernel_launch(void* const* d_in, const int* in_sizes, int n_in,
                              void* d_out, int out_size)
{
    (void)in_sizes; (void)n_in; (void)out_size;
    const float* Q   = (const float*)d_in[0];
    const float* K   = (const float*)d_in[1];
    const float* V   = (const float*)d_in[2];
    const float* qm  = (const float*)d_in[3];
    const float* km  = (const float*)d_in[4];
    const float* am  = (const float*)d_in[5];
    const float* WQ  = (const float*)d_in[6];
    const float* WK  = (const float*)d_in[7];
    const float* WV  = (const float*)d_in[8];
    const float* WO  = (const float*)d_in[9];
    float* out = (float*)d_out;

    const int gemm_smem = 2 * 2 * 128 * 36 * (int)sizeof(float);   // 73728
    cudaFuncSetAttribute(gemm_qkv,
                         cudaFuncAttributeMaxDynamicSharedMemorySize, gemm_smem);
    cudaFuncSetAttribute(gemm_out,
                         cudaFuncAttributeMaxDynamicSharedMemorySize, gemm_smem);

    round_w<<<dim3(DM * DM / 4 / 256, 4), 256>>>(WQ, WK, WV, WO);
    pack_mask<<<(BSZ * SEQ * SEQ) / 1024, 256>>>(am);

    gemm_qkv<<<dim3(DM / 128, MR / 128, 3), 256, gemm_smem>>>(Q, K, V, qm, km);

    const int attn_smem = (128 * 76 + 2 * 64 * 68 + 2 * 64 * 72)
                          * (int)sizeof(float);  // 110592
    cudaFuncSetAttribute(attn_tf32, cudaFuncAttributeMaxDynamicSharedMemorySize,
                         attn_smem);
    attn_tf32<<<dim3(SEQ / 128, NH, BSZ), 128, attn_smem>>>(km);

    gemm_out<<<dim3(DM / 128, MR / 128), 256, gemm_smem>>>(km, out);
}